// round 5
// baseline (speedup 1.0000x reference)
#include <cuda_runtime.h>
#include <cstdint>

// SPP: out = concat([x, maxpool5(x), maxpool9(x), maxpool13(x)], axis=1)
// x: (16, 512, 64, 64) fp32 -> out: (16, 2048, 64, 64) fp32
//
// maxpool9 = mp5(mp5(x)); maxpool13 = mp5(mp9)  (exact with -inf pad).
// Each 5x5 pool separable: row-max5 then col-max5.
//
// R4: TWO planes per CTA (dynamic smem, 71.8 KB):
//  - h-pass: thread owns one row, 32-col segment: 10 LDS.128 -> 8 STS.128
//  - v-pass: thread owns 8 rows x 4 cols: 12 LDS.128 -> 8 STS.128 + 8 STG.128
//  - B has per-plane guard rows (-inf) -> v-pass fully unpredicated
//  - last level skips the A writeback (never re-read)
// All smem phases conflict-free (pitch 68; row-major lane mappings).

#define P 68                         // smem row pitch in floats (16B-aligned rows)
#define A_FLOATS (4 + 128 * P)       // 4-float left guard + 128 rows
#define B_FLOATS (136 * P)           // 2 planes x (2 guard + 64 + 2 guard) rows
#define SMEM_BYTES ((A_FLOATS + B_FLOATS) * 4)

__device__ __forceinline__ float fmax5(float a, float b, float c, float d, float e) {
    return fmaxf(fmaxf(fmaxf(a, b), fmaxf(c, d)), e);
}

__device__ __forceinline__ float4 vmax5(float4 a, float4 b, float4 c, float4 d, float4 e) {
    float4 r;
    r.x = fmax5(a.x, b.x, c.x, d.x, e.x);
    r.y = fmax5(a.y, b.y, c.y, d.y, e.y);
    r.z = fmax5(a.z, b.z, c.z, d.z, e.z);
    r.w = fmax5(a.w, b.w, c.w, d.w, e.w);
    return r;
}

__global__ __launch_bounds__(256) void spp_kernel(const float* __restrict__ x,
                                                  float* __restrict__ out) {
    extern __shared__ __align__(16) float smem[];
    float* Araw = smem;            // [4 + 128*P]
    float* A    = smem + 4;        // A[row*P + col], rows 0..127 (2 planes stacked)
    float* B    = smem + A_FLOATS; // per-plane: rows 0,1 guard | 2..65 data | 66,67 guard

    const float NI = __int_as_float(0xff800000);
    const float4 NI4 = make_float4(NI, NI, NI, NI);

    const int tid   = threadIdx.x;
    const int pidx0 = blockIdx.x << 1;           // first of 2 consecutive planes
    const int n     = pidx0 >> 9;
    const int c0    = pidx0 & 511;               // c0 even -> both planes same n

    const float* gx    = x + (size_t)pidx0 * 4096;          // 2 planes, contiguous
    float*       gout0 = out + ((size_t)n * 2048 + c0) * 4096;

    // ---- Prologue: load 2 planes into A, copy to out chunk 0, init guards ----
    {
        const float4* gx4 = (const float4*)gx;
        float4*       go4 = (float4*)gout0;
#pragma unroll
        for (int i = 0; i < 8; i++) {
            int idx  = tid + i * 256;            // float4 index 0..2047
            float4 v = gx4[idx];
            go4[idx] = v;
            int row = idx >> 4;                  // 0..127
            int c4  = idx & 15;
            *(float4*)&A[row * P + c4 * 4] = v;
        }
        if (tid < 128) *(float4*)&A[tid * P + 64] = NI4;   // right pads cols 64..67
        if (tid == 128) *(float4*)&Araw[0] = NI4;          // left guard before row 0
        if (tid < 136) {                                   // B guard rows (8 rows x 17 f4)
            int gr = tid / 17, c4 = tid % 17;
            int plane = gr >> 2, q = gr & 3;
            int lrow = (q < 2) ? q : (64 + q);             // local rows 0,1,66,67
            *(float4*)&B[(plane * 68 + lrow) * P + c4 * 4] = NI4;
        }
    }
    __syncthreads();

    // h-pass mapping: one row per thread, 32-col segment
    const int hrow  = tid & 127;                 // global row 0..127
    const int hseg  = (tid >> 7) << 5;           // 0 or 32
    const int hpl   = hrow >> 6;
    const int hrl   = hrow & 63;
    const float* hsrc = &A[hrow * P + hseg - 4];
    float*       hdst = &B[(hpl * 68 + 2 + hrl) * P + hseg];

    // v-pass mapping: 4 cols x 8 rows per thread
    const int vc4  = tid & 15;                   // float4 column 0..15
    const int vr0g = (tid >> 4) << 3;            // global row base 0..120 (plane-aligned)
    const int vpl  = vr0g >> 6;
    const int vrl  = vr0g & 63;
    const float* vsrc = &B[(vpl * 68 + vrl) * P + vc4 * 4];   // = local row (vrl-2)+guard
    float*       vdstA = &A[vr0g * P + vc4 * 4];
    float*       vg    = gout0 + (size_t)vpl * 4096;          // this thread's plane base

#pragma unroll
    for (int level = 0; level < 3; level++) {
        // ---- horizontal max5: A -> B (10 LDS.128, 8 STS.128, unpredicated) ----
        {
            float w[40];
#pragma unroll
            for (int k = 0; k < 10; k++) {
                float4 v = *(const float4*)(hsrc + 4 * k);
                w[4 * k + 0] = v.x; w[4 * k + 1] = v.y;
                w[4 * k + 2] = v.z; w[4 * k + 3] = v.w;
            }
#pragma unroll
            for (int m = 0; m < 8; m++) {
                float4 o;
                o.x = fmax5(w[4 * m + 2], w[4 * m + 3], w[4 * m + 4], w[4 * m + 5], w[4 * m + 6]);
                o.y = fmax5(w[4 * m + 3], w[4 * m + 4], w[4 * m + 5], w[4 * m + 6], w[4 * m + 7]);
                o.z = fmax5(w[4 * m + 4], w[4 * m + 5], w[4 * m + 6], w[4 * m + 7], w[4 * m + 8]);
                o.w = fmax5(w[4 * m + 5], w[4 * m + 6], w[4 * m + 7], w[4 * m + 8], w[4 * m + 9]);
                *(float4*)(hdst + 4 * m) = o;
            }
        }
        __syncthreads();

        // ---- vertical max5: B -> A (+final STG.128), unpredicated via guards ----
        {
            float4 v[12];
#pragma unroll
            for (int k = 0; k < 12; k++)
                v[k] = *(const float4*)(vsrc + k * P);

            float4* gl4 = (float4*)(vg + (size_t)(level + 1) * 512 * 4096);
#pragma unroll
            for (int j = 0; j < 8; j++) {
                float4 o = vmax5(v[j], v[j + 1], v[j + 2], v[j + 3], v[j + 4]);
                if (level < 2)
                    *(float4*)(vdstA + j * P) = o;
                gl4[(size_t)(vrl + j) * 16 + vc4] = o;
            }
        }
        if (level < 2) __syncthreads();
    }
}

extern "C" void kernel_launch(void* const* d_in, const int* in_sizes, int n_in,
                              void* d_out, int out_size) {
    const float* x = (const float*)d_in[0];
    float* out = (float*)d_out;
    cudaFuncSetAttribute(spp_kernel, cudaFuncAttributeMaxDynamicSharedMemorySize,
                         SMEM_BYTES);
    spp_kernel<<<4096, 256, SMEM_BYTES>>>(x, out);  // 2 planes per CTA
}